// round 1
// baseline (speedup 1.0000x reference)
#include <cuda_runtime.h>
#include <cuda_bf16.h>
#include <math.h>

// Problem constants
#define BB   16
#define NO   512
#define NM   128
#define NV   64
#define EE   256
#define HH   16
#define DKK  16
#define MSS  8
#define FFF  512

// ---------------- scratch (device globals; no allocation allowed) ------------
__device__ float g_q   [BB * NO * EE];        // up to 512 rows
__device__ float g_k   [BB * NM * EE];
__device__ float g_v   [BB * NM * EE];
__device__ float g_ctx [BB * NO * EE];
__device__ float g_t1  [BB * NO * EE];
__device__ float g_out1[BB * NO * EE];
__device__ float g_h   [BB * NO * FFF];
__device__ float g_cat [BB * NM * (2 * EE)];
__device__ float g_Aproc   [BB * NO * NM];
__device__ float g_Aoff    [BB * NV * NM];
__device__ float g_Aprocing[BB * NM * NM];
__device__ float g_Aon     [BB * NM * NM];
__device__ int   g_mask_mode;  // 0=float32, 1=int32, 2=uint8

// ---------------- mask dtype sniffing ---------------------------------------
__global__ void detect_mask_kernel(const unsigned int* __restrict__ w, int nwords) {
    __shared__ int sawF, sawOther;
    if (threadIdx.x == 0) { sawF = 0; sawOther = 0; }
    __syncthreads();
    int f = 0, o = 0;
    for (int i = threadIdx.x; i < nwords; i += blockDim.x) {
        unsigned int x = w[i];
        if (x == 0x3F800000u) f = 1;
        else if (x != 0u && x != 1u) o = 1;
    }
    if (f) atomicOr(&sawF, 1);
    if (o) atomicOr(&sawOther, 1);
    __syncthreads();
    if (threadIdx.x == 0) g_mask_mode = sawF ? 0 : (sawOther ? 2 : 1);
}

__device__ __forceinline__ bool read_mask(const void* p, size_t i) {
    int m = g_mask_mode;
    if (m == 0) return ((const float*)p)[i] != 0.0f;
    if (m == 1) return ((const int*)p)[i] != 0;
    return ((const unsigned char*)p)[i] != 0;
}

// ---------------- adjacency kernels ------------------------------------------
// A_proc_norm: per (b,o) row, keep only the min nonzero masked entry -> 1.0
__global__ void aproc_kernel(const float* __restrict__ proc, const void* maskdyn,
                             float* __restrict__ out) {
    int o = blockIdx.x, b = blockIdx.y;
    int j = threadIdx.x;            // 128 threads, one per machine
    size_t idx = ((size_t)b * NO + o) * NM + j;
    float pv = read_mask(maskdyn, idx) ? proc[idx] : 0.0f;
    float nz = (pv == 0.0f) ? 1e30f : pv;
    int lane = j & 31, wid = j >> 5;
    float m = nz;
    #pragma unroll
    for (int off = 16; off; off >>= 1) m = fminf(m, __shfl_xor_sync(~0u, m, off));
    __shared__ float red[4];
    if (lane == 0) red[wid] = m;
    __syncthreads();
    m = fminf(fminf(red[0], red[1]), fminf(red[2], red[3]));
    out[idx] = (pv != 0.0f && pv == m) ? 1.0f : 0.0f;
}

// A_procing = !(mask2);  tt = mask2 ? trans : TRANS_MAX+1
__global__ void procing_tt_kernel(const float* __restrict__ trans, const void* maskma,
                                  float* __restrict__ outProc, float* __restrict__ outTT) {
    int i = blockIdx.x, b = blockIdx.y, j = threadIdx.x;  // 128 threads
    bool mi = read_mask(maskma, (size_t)b * NM + i);
    bool mj = read_mask(maskma, (size_t)b * NM + j);
    bool m2 = mi && mj;
    size_t idx = ((size_t)b * NM + i) * NM + j;
    outProc[idx] = m2 ? 0.0f : 1.0f;
    outTT[idx]   = m2 ? trans[idx] : 101.0f;
}

// out = 1 - (x - min)/(max - min)   (per-batch min/max over n elems)
__global__ void inv_norm_kernel(const float* __restrict__ in, float* __restrict__ out, int n) {
    int b = blockIdx.x;
    const float* ip = in + (size_t)b * n;
    float* op = out + (size_t)b * n;
    int t = threadIdx.x, lane = t & 31, wid = t >> 5;
    float mn = 1e30f, mx = -1e30f;
    for (int i = t; i < n; i += blockDim.x) {
        float v = ip[i];
        mn = fminf(mn, v); mx = fmaxf(mx, v);
    }
    #pragma unroll
    for (int off = 16; off; off >>= 1) {
        mn = fminf(mn, __shfl_xor_sync(~0u, mn, off));
        mx = fmaxf(mx, __shfl_xor_sync(~0u, mx, off));
    }
    __shared__ float smn[8], smx[8];
    if (lane == 0) { smn[wid] = mn; smx[wid] = mx; }
    __syncthreads();
    float gmn = 1e30f, gmx = -1e30f;
    #pragma unroll
    for (int i = 0; i < 8; i++) { gmn = fminf(gmn, smn[i]); gmx = fmaxf(gmx, smx[i]); }
    float inv = 1.0f / (gmx - gmn);
    for (int i = t; i < n; i += blockDim.x)
        op[i] = 1.0f - (ip[i] - gmn) * inv;
}

// ---------------- SGEMM: C[b] = act(A[b] @ W + bias) -------------------------
// A: [B, R, K] tight; W: [K, N]; C: [B, R, N] tight.  R%64==0, N%64==0, K%16==0.
#define BM 64
#define BN 64
#define BKK 16
__global__ __launch_bounds__(256) void sgemm_kernel(
    const float* __restrict__ A, const float* __restrict__ W,
    const float* __restrict__ bias, float* __restrict__ C,
    int R, int K, int N, int relu)
{
    int b = blockIdx.z;
    A += (size_t)b * R * K;
    C += (size_t)b * R * N;
    int rowBase = blockIdx.y * BM, colBase = blockIdx.x * BN;
    __shared__ float As[BKK][BM + 1];
    __shared__ float Bs[BKK][BN + 1];
    int tid = threadIdx.x;
    int tx = tid & 15, ty = tid >> 4;
    float acc[4][4] = {};
    for (int k0 = 0; k0 < K; k0 += BKK) {
        #pragma unroll
        for (int l = 0; l < 4; l++) {
            int idx = tid + l * 256;
            int ar = idx >> 4, ac = idx & 15;
            As[ac][ar] = A[(size_t)(rowBase + ar) * K + k0 + ac];
        }
        #pragma unroll
        for (int l = 0; l < 4; l++) {
            int idx = tid + l * 256;
            int br = idx >> 6, bc = idx & 63;
            Bs[br][bc] = W[(size_t)(k0 + br) * N + colBase + bc];
        }
        __syncthreads();
        #pragma unroll
        for (int k = 0; k < BKK; k++) {
            float a[4], w[4];
            #pragma unroll
            for (int i = 0; i < 4; i++) a[i] = As[k][ty * 4 + i];
            #pragma unroll
            for (int j = 0; j < 4; j++) w[j] = Bs[k][tx * 4 + j];
            #pragma unroll
            for (int i = 0; i < 4; i++)
                #pragma unroll
                for (int j = 0; j < 4; j++) acc[i][j] += a[i] * w[j];
        }
        __syncthreads();
    }
    #pragma unroll
    for (int i = 0; i < 4; i++) {
        int r = rowBase + ty * 4 + i;
        #pragma unroll
        for (int j = 0; j < 4; j++) {
            int c = colBase + tx * 4 + j;
            float v = acc[i][j];
            if (bias) v += bias[c];
            if (relu) v = fmaxf(v, 0.0f);
            C[(size_t)r * N + c] = v;
        }
    }
}

// ---------------- fused attention: dot + mixed-score MLP + softmax + attn@V --
// One block per (b, h, row-tile). C = 128 fixed. 128 threads (one per column).
__global__ __launch_bounds__(128) void attn_kernel(
    const float* __restrict__ Q, const float* __restrict__ K,
    const float* __restrict__ V, const float* __restrict__ cost,
    float* __restrict__ ctx,
    const float* __restrict__ mW1, const float* __restrict__ mb1,
    const float* __restrict__ mW2, const float* __restrict__ mb2,
    int R, int rowsPerBlock)
{
    const int C = 128;
    int bh = blockIdx.x;
    int b = bh >> 4, h = bh & 15;
    int r0 = blockIdx.y * rowsPerBlock;
    int tid = threadIdx.x;
    int lane = tid & 31, wid = tid >> 5;

    __shared__ float Ks[128][17], Vs[128][17];
    __shared__ float qs[16], psh[128], red[4], part[8][16];
    __shared__ float w1d[8], w1c[8], b1s[8], w2s[8], b2s[1];

    if (tid < 8) {
        w1d[tid] = mW1[h * 16 + tid];       // mixW1[h][0][s]
        w1c[tid] = mW1[h * 16 + 8 + tid];   // mixW1[h][1][s]
        b1s[tid] = mb1[h * 8 + tid];
        w2s[tid] = mW2[h * 8 + tid];
    }
    if (tid == 0) b2s[0] = mb2[h];

    for (int idx = tid; idx < C * 16; idx += 128) {
        int c = idx >> 4, d = idx & 15;
        size_t g = ((size_t)b * C + c) * EE + h * 16 + d;
        Ks[c][d] = K[g];
        Vs[c][d] = V[g];
    }
    __syncthreads();

    for (int r = r0; r < r0 + rowsPerBlock; r++) {
        if (tid < 16) qs[tid] = Q[((size_t)b * R + r) * EE + h * 16 + tid];
        __syncthreads();

        int c = tid;
        float dot = 0.0f;
        #pragma unroll
        for (int d = 0; d < 16; d++) dot += qs[d] * Ks[c][d];
        dot *= 0.25f;  // 1/sqrt(16)
        float cv = cost[((size_t)b * R + r) * C + c];
        float sc = b2s[0];
        #pragma unroll
        for (int s = 0; s < 8; s++) {
            float t = dot * w1d[s] + cv * w1c[s] + b1s[s];
            sc += fmaxf(t, 0.0f) * w2s[s];
        }
        // block softmax over 128 columns
        float m = sc;
        #pragma unroll
        for (int off = 16; off; off >>= 1) m = fmaxf(m, __shfl_xor_sync(~0u, m, off));
        if (lane == 0) red[wid] = m;
        __syncthreads();
        m = fmaxf(fmaxf(red[0], red[1]), fmaxf(red[2], red[3]));
        float p = expf(sc - m);
        __syncthreads();
        float ssum = p;
        #pragma unroll
        for (int off = 16; off; off >>= 1) ssum += __shfl_xor_sync(~0u, ssum, off);
        if (lane == 0) red[wid] = ssum;
        __syncthreads();
        ssum = red[0] + red[1] + red[2] + red[3];
        psh[tid] = p / ssum;
        __syncthreads();

        // ctx[d] = sum_c p[c] * V[c][d]
        int d = tid & 15, g = tid >> 4;
        float acc = 0.0f;
        #pragma unroll
        for (int i = 0; i < 16; i++) {
            int cc = g * 16 + i;
            acc += psh[cc] * Vs[cc][d];
        }
        part[g][d] = acc;
        __syncthreads();
        if (tid < 16) {
            float s2 = 0.0f;
            #pragma unroll
            for (int gg = 0; gg < 8; gg++) s2 += part[gg][tid];
            ctx[((size_t)b * R + r) * EE + h * 16 + tid] = s2;
        }
        __syncthreads();
    }
}

// ---------------- fused residual-add + layernorm ------------------------------
// one block (256 threads) per row; out row stride / column offset for concat
__global__ __launch_bounds__(256) void add_ln_kernel(
    const float* __restrict__ x, const float* __restrict__ res,
    float* __restrict__ out, int outStride, int colOff)
{
    int row = blockIdx.x;
    int t = threadIdx.x, lane = t & 31, wid = t >> 5;
    float v = x[(size_t)row * EE + t] + res[(size_t)row * EE + t];
    __shared__ float red[8];
    float s = v;
    #pragma unroll
    for (int off = 16; off; off >>= 1) s += __shfl_xor_sync(~0u, s, off);
    if (lane == 0) red[wid] = s;
    __syncthreads();
    s = 0.0f;
    #pragma unroll
    for (int i = 0; i < 8; i++) s += red[i];
    float mean = s * (1.0f / EE);
    float d = v - mean;
    __syncthreads();
    float s2 = d * d;
    #pragma unroll
    for (int off = 16; off; off >>= 1) s2 += __shfl_xor_sync(~0u, s2, off);
    if (lane == 0) red[wid] = s2;
    __syncthreads();
    s2 = 0.0f;
    #pragma unroll
    for (int i = 0; i < 8; i++) s2 += red[i];
    float var = s2 * (1.0f / EE);
    float rstd = rsqrtf(var + 1e-5f);
    out[(size_t)row * outStride + colOff + t] = d * rstd;
}

// ---------------- host orchestration ------------------------------------------
static float* symaddr_f(const void* sym) {
    void* p = nullptr;
    cudaGetSymbolAddress(&p, sym);
    return (float*)p;
}

extern "C" void kernel_launch(void* const* d_in, const int* in_sizes, int n_in,
                              void* d_out, int out_size) {
    const float* ope   = (const float*)d_in[0];
    const float* maEmb = (const float*)d_in[1];
    const float* veh   = (const float*)d_in[2];
    const float* proc  = (const float*)d_in[3];
    // d_in[4] offload_trans_time: unused by reference
    const float* trans = (const float*)d_in[5];
    const float* mvp   = (const float*)d_in[6];
    const void*  mdyn  = d_in[7];
    const void*  mma   = d_in[8];
    const float* Wq = (const float*)d_in[9];
    const float* Wk = (const float*)d_in[10];
    const float* Wv = (const float*)d_in[11];
    const float* Wo = (const float*)d_in[12];
    const float* mixW1 = (const float*)d_in[13];
    const float* mixb1 = (const float*)d_in[14];
    const float* mixW2 = (const float*)d_in[15];
    const float* mixb2 = (const float*)d_in[16];
    const float* ffW1 = (const float*)d_in[17];
    const float* ffb1 = (const float*)d_in[18];
    const float* ffW2 = (const float*)d_in[19];
    const float* ffb2 = (const float*)d_in[20];
    const float* mpW = (const float*)d_in[21];
    const float* mpB = (const float*)d_in[22];

    float* q    = symaddr_f((const void*)g_q);
    float* kbuf = symaddr_f((const void*)g_k);
    float* vbuf = symaddr_f((const void*)g_v);
    float* ctx  = symaddr_f((const void*)g_ctx);
    float* t1   = symaddr_f((const void*)g_t1);
    float* out1 = symaddr_f((const void*)g_out1);
    float* hbuf = symaddr_f((const void*)g_h);
    float* cat  = symaddr_f((const void*)g_cat);
    float* aproc = symaddr_f((const void*)g_Aproc);
    float* aoff  = symaddr_f((const void*)g_Aoff);
    float* aping = symaddr_f((const void*)g_Aprocing);
    float* aon   = symaddr_f((const void*)g_Aon);

    // 1) mask dtype sniff (safe word count = elems/4, valid for all 3 dtypes)
    detect_mask_kernel<<<1, 256>>>((const unsigned int*)mdyn, (BB * NO * NM) / 4);

    // 2) adjacency
    aproc_kernel<<<dim3(NO, BB), NM>>>(proc, mdyn, aproc);
    procing_tt_kernel<<<dim3(NM, BB), NM>>>(trans, mma, aping, aon);
    inv_norm_kernel<<<BB, 256>>>(mvp, aoff, NV * NM);
    inv_norm_kernel<<<BB, 256>>>(aon, aon, NM * NM);   // in-place: read pass then write pass

    float* outF = (float*)d_out;
    float* opeOut = outF;                                  // [16,512,256]
    float* maOut  = outF + (size_t)BB * NO * EE;           // [16,128,256]
    float* vehOut = maOut + (size_t)BB * NM * EE;          // [16,64,256]

    auto run_block = [&](int i, const float* row, const float* col, int R,
                         const float* cost, float* dst, int dstStride, int dstColOff) {
        const float* wq = Wq + (size_t)i * EE * EE;
        const float* wk = Wk + (size_t)i * EE * EE;
        const float* wv = Wv + (size_t)i * EE * EE;
        const float* wo = Wo + (size_t)i * EE * EE;
        const float* mw1 = mixW1 + (size_t)i * HH * 2 * MSS;
        const float* mb1 = mixb1 + (size_t)i * HH * MSS;
        const float* mw2 = mixW2 + (size_t)i * HH * MSS;
        const float* mb2 = mixb2 + (size_t)i * HH;
        const float* fw1 = ffW1 + (size_t)i * EE * FFF;
        const float* fb1 = ffb1 + (size_t)i * FFF;
        const float* fw2 = ffW2 + (size_t)i * FFF * EE;
        const float* fb2 = ffb2 + (size_t)i * EE;

        sgemm_kernel<<<dim3(EE / BN, R / BM, BB), 256>>>(row, wq, nullptr, q, R, EE, EE, 0);
        sgemm_kernel<<<dim3(EE / BN, NM / BM, BB), 256>>>(col, wk, nullptr, kbuf, NM, EE, EE, 0);
        sgemm_kernel<<<dim3(EE / BN, NM / BM, BB), 256>>>(col, wv, nullptr, vbuf, NM, EE, EE, 0);
        attn_kernel<<<dim3(BB * HH, R / 32), 128>>>(q, kbuf, vbuf, cost, ctx,
                                                    mw1, mb1, mw2, mb2, R, 32);
        sgemm_kernel<<<dim3(EE / BN, R / BM, BB), 256>>>(ctx, wo, nullptr, t1, R, EE, EE, 0);
        add_ln_kernel<<<BB * R, 256>>>(t1, row, out1, EE, 0);
        sgemm_kernel<<<dim3(FFF / BN, R / BM, BB), 256>>>(out1, fw1, fb1, hbuf, R, EE, FFF, 1);
        sgemm_kernel<<<dim3(EE / BN, R / BM, BB), 256>>>(hbuf, fw2, fb2, t1, R, FFF, EE, 0);
        add_ln_kernel<<<BB * R, 256>>>(t1, out1, dst, dstStride, dstColOff);
    };

    run_block(0, ope,   maEmb, NO, aproc, opeOut, EE, 0);
    run_block(1, veh,   maEmb, NV, aoff,  vehOut, EE, 0);
    run_block(2, maEmb, maEmb, NM, aping, cat, 2 * EE, 0);
    run_block(3, maEmb, maEmb, NM, aon,   cat, 2 * EE, EE);

    // ma_out = concat(ma1, ma2) @ maprojW + maprojb
    sgemm_kernel<<<dim3(EE / BN, NM / BM, BB), 256>>>(cat, mpW, mpB, maOut, NM, 2 * EE, EE, 0);
}

// round 3
// speedup vs baseline: 1.1466x; 1.1466x over previous
#include <cuda_runtime.h>
#include <cuda_bf16.h>
#include <math.h>

// Problem constants
#define BB   16
#define NO   512
#define NM   128
#define NV   64
#define EE   256
#define HH   16
#define DKK  16
#define MSS  8
#define FFF  512

// ---------------- scratch (device globals; no allocation allowed) ------------
__device__ float g_q   [BB * NO * EE];
__device__ float g_k   [BB * NM * EE];
__device__ float g_v   [BB * NM * EE];
__device__ float g_ctx [BB * NO * EE];
__device__ float g_t1  [BB * NO * EE];
__device__ float g_out1[BB * NO * EE];
__device__ float g_h   [BB * NO * FFF];
__device__ float g_cat [BB * NM * (2 * EE)];
__device__ float g_Aproc   [BB * NO * NM];
__device__ float g_Aoff    [BB * NV * NM];
__device__ float g_Aprocing[BB * NM * NM];
__device__ float g_Aon     [BB * NM * NM];
__device__ int   g_mask_mode;  // 0=float32, 1=int32, 2=uint8

// ---------------- mask dtype sniffing ---------------------------------------
__global__ void detect_mask_kernel(const unsigned int* __restrict__ w, int nwords) {
    __shared__ int sawF, sawOther;
    if (threadIdx.x == 0) { sawF = 0; sawOther = 0; }
    __syncthreads();
    int f = 0, o = 0;
    for (int i = threadIdx.x; i < nwords; i += blockDim.x) {
        unsigned int x = w[i];
        if (x == 0x3F800000u) f = 1;
        else if (x != 0u && x != 1u) o = 1;
    }
    if (f) atomicOr(&sawF, 1);
    if (o) atomicOr(&sawOther, 1);
    __syncthreads();
    if (threadIdx.x == 0) g_mask_mode = sawF ? 0 : (sawOther ? 2 : 1);
}

__device__ __forceinline__ bool read_mask(const void* p, size_t i) {
    int m = g_mask_mode;
    if (m == 0) return ((const float*)p)[i] != 0.0f;
    if (m == 1) return ((const int*)p)[i] != 0;
    return ((const unsigned char*)p)[i] != 0;
}

// ---------------- adjacency kernels ------------------------------------------
__global__ void aproc_kernel(const float* __restrict__ proc, const void* maskdyn,
                             float* __restrict__ out) {
    int o = blockIdx.x, b = blockIdx.y;
    int j = threadIdx.x;            // 128 threads, one per machine
    size_t idx = ((size_t)b * NO + o) * NM + j;
    float pv = read_mask(maskdyn, idx) ? proc[idx] : 0.0f;
    float nz = (pv == 0.0f) ? 1e30f : pv;
    int lane = j & 31, wid = j >> 5;
    float m = nz;
    #pragma unroll
    for (int off = 16; off; off >>= 1) m = fminf(m, __shfl_xor_sync(~0u, m, off));
    __shared__ float red[4];
    if (lane == 0) red[wid] = m;
    __syncthreads();
    m = fminf(fminf(red[0], red[1]), fminf(red[2], red[3]));
    out[idx] = (pv != 0.0f && pv == m) ? 1.0f : 0.0f;
}

__global__ void procing_tt_kernel(const float* __restrict__ trans, const void* maskma,
                                  float* __restrict__ outProc, float* __restrict__ outTT) {
    int i = blockIdx.x, b = blockIdx.y, j = threadIdx.x;  // 128 threads
    bool mi = read_mask(maskma, (size_t)b * NM + i);
    bool mj = read_mask(maskma, (size_t)b * NM + j);
    bool m2 = mi && mj;
    size_t idx = ((size_t)b * NM + i) * NM + j;
    outProc[idx] = m2 ? 0.0f : 1.0f;
    outTT[idx]   = m2 ? trans[idx] : 101.0f;
}

__global__ void inv_norm_kernel(const float* __restrict__ in, float* __restrict__ out, int n) {
    int b = blockIdx.x;
    const float* ip = in + (size_t)b * n;
    float* op = out + (size_t)b * n;
    int t = threadIdx.x, lane = t & 31, wid = t >> 5;
    float mn = 1e30f, mx = -1e30f;
    for (int i = t; i < n; i += blockDim.x) {
        float v = ip[i];
        mn = fminf(mn, v); mx = fmaxf(mx, v);
    }
    #pragma unroll
    for (int off = 16; off; off >>= 1) {
        mn = fminf(mn, __shfl_xor_sync(~0u, mn, off));
        mx = fmaxf(mx, __shfl_xor_sync(~0u, mx, off));
    }
    __shared__ float smn[8], smx[8];
    if (lane == 0) { smn[wid] = mn; smx[wid] = mx; }
    __syncthreads();
    float gmn = 1e30f, gmx = -1e30f;
    #pragma unroll
    for (int i = 0; i < 8; i++) { gmn = fminf(gmn, smn[i]); gmx = fmaxf(gmx, smx[i]); }
    float inv = 1.0f / (gmx - gmn);
    for (int i = t; i < n; i += blockDim.x)
        op[i] = 1.0f - (ip[i] - gmn) * inv;
}

// ---------------- TF32 tensor-core GEMM --------------------------------------
// C[b] = act(A[b] @ W + bias).  A: [B,R,K], W: [K,N], C: [B,R,N].
// CTA tile 128x64, K-step 32. 8 warps: 4 along M (32 rows), 2 along N (32 cols).
// Row bounds guarded (supports R=64 with BM=128). K%32==0, N%64==0 required.
#define GBM 128
#define GBN 64
#define GBK 32

__device__ __forceinline__ unsigned f2tf32(float x) {
    unsigned u;
    asm("cvt.rna.tf32.f32 %0, %1;" : "=r"(u) : "f"(x));
    return u;
}

__device__ __forceinline__ void mma_tf32(float d[4], const unsigned a[4],
                                         const unsigned bfr[2]) {
    asm volatile(
        "mma.sync.aligned.m16n8k8.row.col.f32.tf32.tf32.f32 "
        "{%0,%1,%2,%3},{%4,%5,%6,%7},{%8,%9},{%0,%1,%2,%3};\n"
        : "+f"(d[0]), "+f"(d[1]), "+f"(d[2]), "+f"(d[3])
        : "r"(a[0]), "r"(a[1]), "r"(a[2]), "r"(a[3]),
          "r"(bfr[0]), "r"(bfr[1]));
}

__global__ __launch_bounds__(256) void gemm_tf32_kernel(
    const float* __restrict__ A, const float* __restrict__ W,
    const float* __restrict__ bias, float* __restrict__ C,
    int R, int K, int N, int relu)
{
    int b = blockIdx.z;
    A += (size_t)b * R * K;
    C += (size_t)b * R * N;
    int rowBase = blockIdx.y * GBM;
    int colBase = blockIdx.x * GBN;

    __shared__ float As[GBM][GBK + 4];   // 128 x 36
    __shared__ float Bs[GBK][GBN + 4];   // 32 x 68

    int tid = threadIdx.x;
    int warp = tid >> 5, lane = tid & 31;
    int g = lane >> 2, tig = lane & 3;
    int wm = (warp & 3) * 32;       // 4 warps along M
    int wn = (warp >> 2) * 32;      // 2 warps along N

    float acc[2][4][4];
    #pragma unroll
    for (int mi = 0; mi < 2; mi++)
        #pragma unroll
        for (int nj = 0; nj < 4; nj++)
            #pragma unroll
            for (int e = 0; e < 4; e++) acc[mi][nj][e] = 0.0f;

    for (int k0 = 0; k0 < K; k0 += GBK) {
        // load A tile 128x32 (1024 float4, 4 per thread), row-guarded
        #pragma unroll
        for (int i = 0; i < 4; i++) {
            int f = tid + i * 256;
            int k4 = f & 7, m = f >> 3;
            float4 v = make_float4(0.f, 0.f, 0.f, 0.f);
            if (rowBase + m < R)
                v = *(const float4*)&A[(size_t)(rowBase + m) * K + k0 + k4 * 4];
            v.x = __uint_as_float(f2tf32(v.x));
            v.y = __uint_as_float(f2tf32(v.y));
            v.z = __uint_as_float(f2tf32(v.z));
            v.w = __uint_as_float(f2tf32(v.w));
            *(float4*)&As[m][k4 * 4] = v;
        }
        // load B tile 32x64 (512 float4, 2 per thread)
        #pragma unroll
        for (int i = 0; i < 2; i++) {
            int f = tid + i * 256;
            int n4 = f & 15, k = f >> 4;
            float4 v = *(const float4*)&W[(size_t)(k0 + k) * N + colBase + n4 * 4];
            v.x = __uint_as_float(f2tf32(v.x));
            v.y = __uint_as_float(f2tf32(v.y));
            v.z = __uint_as_float(f2tf32(v.z));
            v.w = __uint_as_float(f2tf32(v.w));
            *(float4*)&Bs[k][n4 * 4] = v;
        }
        __syncthreads();

        #pragma unroll
        for (int kk = 0; kk < GBK; kk += 8) {
            unsigned afr[2][4], bfr[4][2];
            #pragma unroll
            for (int mi = 0; mi < 2; mi++) {
                int r = wm + mi * 16 + g;
                afr[mi][0] = __float_as_uint(As[r][kk + tig]);
                afr[mi][1] = __float_as_uint(As[r + 8][kk + tig]);
                afr[mi][2] = __float_as_uint(As[r][kk + tig + 4]);
                afr[mi][3] = __float_as_uint(As[r + 8][kk + tig + 4]);
            }
            #pragma unroll
            for (int nj = 0; nj < 4; nj++) {
                int c = wn + nj * 8 + g;
                bfr[nj][0] = __float_as_uint(Bs[kk + tig][c]);
                bfr[nj][1] = __float_as_uint(Bs[kk + tig + 4][c]);
            }
            #pragma unroll
            for (int mi = 0; mi < 2; mi++)
                #pragma unroll
                for (int nj = 0; nj < 4; nj++)
                    mma_tf32(acc[mi][nj], afr[mi], bfr[nj]);
        }
        __syncthreads();
    }

    // epilogue: bias + relu + guarded stores
    #pragma unroll
    for (int mi = 0; mi < 2; mi++) {
        #pragma unroll
        for (int nj = 0; nj < 4; nj++) {
            int r0 = rowBase + wm + mi * 16 + g;
            int c0 = colBase + wn + nj * 8 + tig * 2;
            float b0 = 0.f, b1 = 0.f;
            if (bias) { b0 = bias[c0]; b1 = bias[c0 + 1]; }
            float v0 = acc[mi][nj][0] + b0, v1 = acc[mi][nj][1] + b1;
            float v2 = acc[mi][nj][2] + b0, v3 = acc[mi][nj][3] + b1;
            if (relu) {
                v0 = fmaxf(v0, 0.f); v1 = fmaxf(v1, 0.f);
                v2 = fmaxf(v2, 0.f); v3 = fmaxf(v3, 0.f);
            }
            if (r0 < R) {
                float2 p = make_float2(v0, v1);
                *(float2*)&C[(size_t)r0 * N + c0] = p;
            }
            if (r0 + 8 < R) {
                float2 p = make_float2(v2, v3);
                *(float2*)&C[(size_t)(r0 + 8) * N + c0] = p;
            }
        }
    }
}

// ---------------- fused attention: dot + mixed-score MLP + softmax + attn@V --
__global__ __launch_bounds__(128) void attn_kernel(
    const float* __restrict__ Q, const float* __restrict__ K,
    const float* __restrict__ V, const float* __restrict__ cost,
    float* __restrict__ ctx,
    const float* __restrict__ mW1, const float* __restrict__ mb1,
    const float* __restrict__ mW2, const float* __restrict__ mb2,
    int R, int rowsPerBlock)
{
    const int C = 128;
    int bh = blockIdx.x;
    int b = bh >> 4, h = bh & 15;
    int r0 = blockIdx.y * rowsPerBlock;
    int tid = threadIdx.x;
    int lane = tid & 31, wid = tid >> 5;

    __shared__ float Ks[128][17], Vs[128][17];
    __shared__ float qs[16], psh[128], red[4], part[8][16];
    __shared__ float w1d[8], w1c[8], b1s[8], w2s[8], b2s[1];

    if (tid < 8) {
        w1d[tid] = mW1[h * 16 + tid];       // mixW1[h][0][s]
        w1c[tid] = mW1[h * 16 + 8 + tid];   // mixW1[h][1][s]
        b1s[tid] = mb1[h * 8 + tid];
        w2s[tid] = mW2[h * 8 + tid];
    }
    if (tid == 0) b2s[0] = mb2[h];

    for (int idx = tid; idx < C * 16; idx += 128) {
        int c = idx >> 4, d = idx & 15;
        size_t gg = ((size_t)b * C + c) * EE + h * 16 + d;
        Ks[c][d] = K[gg];
        Vs[c][d] = V[gg];
    }
    __syncthreads();

    for (int r = r0; r < r0 + rowsPerBlock; r++) {
        if (tid < 16) qs[tid] = Q[((size_t)b * R + r) * EE + h * 16 + tid];
        __syncthreads();

        int c = tid;
        float dot = 0.0f;
        #pragma unroll
        for (int d = 0; d < 16; d++) dot += qs[d] * Ks[c][d];
        dot *= 0.25f;  // 1/sqrt(16)
        float cv = cost[((size_t)b * R + r) * C + c];
        float sc = b2s[0];
        #pragma unroll
        for (int s = 0; s < 8; s++) {
            float t = dot * w1d[s] + cv * w1c[s] + b1s[s];
            sc += fmaxf(t, 0.0f) * w2s[s];
        }
        float m = sc;
        #pragma unroll
        for (int off = 16; off; off >>= 1) m = fmaxf(m, __shfl_xor_sync(~0u, m, off));
        if (lane == 0) red[wid] = m;
        __syncthreads();
        m = fmaxf(fmaxf(red[0], red[1]), fmaxf(red[2], red[3]));
        float p = expf(sc - m);
        __syncthreads();
        float ssum = p;
        #pragma unroll
        for (int off = 16; off; off >>= 1) ssum += __shfl_xor_sync(~0u, ssum, off);
        if (lane == 0) red[wid] = ssum;
        __syncthreads();
        ssum = red[0] + red[1] + red[2] + red[3];
        psh[tid] = p / ssum;
        __syncthreads();

        int d = tid & 15, gq = tid >> 4;
        float acc = 0.0f;
        #pragma unroll
        for (int i = 0; i < 16; i++) {
            int cc = gq * 16 + i;
            acc += psh[cc] * Vs[cc][d];
        }
        part[gq][d] = acc;
        __syncthreads();
        if (tid < 16) {
            float s2 = 0.0f;
            #pragma unroll
            for (int ggq = 0; ggq < 8; ggq++) s2 += part[ggq][tid];
            ctx[((size_t)b * R + r) * EE + h * 16 + tid] = s2;
        }
        __syncthreads();
    }
}

// ---------------- fused residual-add + layernorm ------------------------------
__global__ __launch_bounds__(256) void add_ln_kernel(
    const float* __restrict__ x, const float* __restrict__ res,
    float* __restrict__ out, int outStride, int colOff)
{
    int row = blockIdx.x;
    int t = threadIdx.x, lane = t & 31, wid = t >> 5;
    float v = x[(size_t)row * EE + t] + res[(size_t)row * EE + t];
    __shared__ float red[8];
    float s = v;
    #pragma unroll
    for (int off = 16; off; off >>= 1) s += __shfl_xor_sync(~0u, s, off);
    if (lane == 0) red[wid] = s;
    __syncthreads();
    s = 0.0f;
    #pragma unroll
    for (int i = 0; i < 8; i++) s += red[i];
    float mean = s * (1.0f / EE);
    float d = v - mean;
    __syncthreads();
    float s2 = d * d;
    #pragma unroll
    for (int off = 16; off; off >>= 1) s2 += __shfl_xor_sync(~0u, s2, off);
    if (lane == 0) red[wid] = s2;
    __syncthreads();
    s2 = 0.0f;
    #pragma unroll
    for (int i = 0; i < 8; i++) s2 += red[i];
    float var = s2 * (1.0f / EE);
    float rstd = rsqrtf(var + 1e-5f);
    out[(size_t)row * outStride + colOff + t] = d * rstd;
}

// ---------------- host orchestration ------------------------------------------
static float* symaddr_f(const void* sym) {
    void* p = nullptr;
    cudaGetSymbolAddress(&p, sym);
    return (float*)p;
}

extern "C" void kernel_launch(void* const* d_in, const int* in_sizes, int n_in,
                              void* d_out, int out_size) {
    const float* ope   = (const float*)d_in[0];
    const float* maEmb = (const float*)d_in[1];
    const float* veh   = (const float*)d_in[2];
    const float* proc  = (const float*)d_in[3];
    // d_in[4] offload_trans_time: unused by reference
    const float* trans = (const float*)d_in[5];
    const float* mvp   = (const float*)d_in[6];
    const void*  mdyn  = d_in[7];
    const void*  mma   = d_in[8];
    const float* Wq = (const float*)d_in[9];
    const float* Wk = (const float*)d_in[10];
    const float* Wv = (const float*)d_in[11];
    const float* Wo = (const float*)d_in[12];
    const float* mixW1 = (const float*)d_in[13];
    const float* mixb1 = (const float*)d_in[14];
    const float* mixW2 = (const float*)d_in[15];
    const float* mixb2 = (const float*)d_in[16];
    const float* ffW1 = (const float*)d_in[17];
    const float* ffb1 = (const float*)d_in[18];
    const float* ffW2 = (const float*)d_in[19];
    const float* ffb2 = (const float*)d_in[20];
    const float* mpW = (const float*)d_in[21];
    const float* mpB = (const float*)d_in[22];

    float* q    = symaddr_f((const void*)g_q);
    float* kbuf = symaddr_f((const void*)g_k);
    float* vbuf = symaddr_f((const void*)g_v);
    float* ctx  = symaddr_f((const void*)g_ctx);
    float* t1   = symaddr_f((const void*)g_t1);
    float* out1 = symaddr_f((const void*)g_out1);
    float* hbuf = symaddr_f((const void*)g_h);
    float* cat  = symaddr_f((const void*)g_cat);
    float* aproc = symaddr_f((const void*)g_Aproc);
    float* aoff  = symaddr_f((const void*)g_Aoff);
    float* aping = symaddr_f((const void*)g_Aprocing);
    float* aon   = symaddr_f((const void*)g_Aon);

    // 1) mask dtype sniff
    detect_mask_kernel<<<1, 256>>>((const unsigned int*)mdyn, (BB * NO * NM) / 4);

    // 2) adjacency
    aproc_kernel<<<dim3(NO, BB), NM>>>(proc, mdyn, aproc);
    procing_tt_kernel<<<dim3(NM, BB), NM>>>(trans, mma, aping, aon);
    inv_norm_kernel<<<BB, 256>>>(mvp, aoff, NV * NM);
    inv_norm_kernel<<<BB, 256>>>(aon, aon, NM * NM);

    float* outF = (float*)d_out;
    float* opeOut = outF;                                  // [16,512,256]
    float* maOut  = outF + (size_t)BB * NO * EE;           // [16,128,256]
    float* vehOut = maOut + (size_t)BB * NM * EE;          // [16,64,256]

    auto gemm = [&](const float* A, const float* W, const float* bias, float* C,
                    int R, int K, int N, int relu) {
        dim3 grid(N / GBN, (R + GBM - 1) / GBM, BB);
        gemm_tf32_kernel<<<grid, 256>>>(A, W, bias, C, R, K, N, relu);
    };

    auto run_block = [&](int i, const float* row, const float* col, int R,
                         const float* cost, float* dst, int dstStride, int dstColOff) {
        const float* wq = Wq + (size_t)i * EE * EE;
        const float* wk = Wk + (size_t)i * EE * EE;
        const float* wv = Wv + (size_t)i * EE * EE;
        const float* wo = Wo + (size_t)i * EE * EE;
        const float* mw1 = mixW1 + (size_t)i * HH * 2 * MSS;
        const float* mb1 = mixb1 + (size_t)i * HH * MSS;
        const float* mw2 = mixW2 + (size_t)i * HH * MSS;
        const float* mb2 = mixb2 + (size_t)i * HH;
        const float* fw1 = ffW1 + (size_t)i * EE * FFF;
        const float* fb1 = ffb1 + (size_t)i * FFF;
        const float* fw2 = ffW2 + (size_t)i * FFF * EE;
        const float* fb2 = ffb2 + (size_t)i * EE;

        gemm(row, wq, nullptr, q, R, EE, EE, 0);
        gemm(col, wk, nullptr, kbuf, NM, EE, EE, 0);
        gemm(col, wv, nullptr, vbuf, NM, EE, EE, 0);
        attn_kernel<<<dim3(BB * HH, R / 32), 128>>>(q, kbuf, vbuf, cost, ctx,
                                                    mw1, mb1, mw2, mb2, R, 32);
        gemm(ctx, wo, nullptr, t1, R, EE, EE, 0);
        add_ln_kernel<<<BB * R, 256>>>(t1, row, out1, EE, 0);
        gemm(out1, fw1, fb1, hbuf, R, EE, FFF, 1);
        gemm(hbuf, fw2, fb2, t1, R, FFF, EE, 0);
        add_ln_kernel<<<BB * R, 256>>>(t1, out1, dst, dstStride, dstColOff);
    };

    run_block(0, ope,   maEmb, NO, aproc, opeOut, EE, 0);
    run_block(1, veh,   maEmb, NV, aoff,  vehOut, EE, 0);
    run_block(2, maEmb, maEmb, NM, aping, cat, 2 * EE, 0);
    run_block(3, maEmb, maEmb, NM, aon,   cat, 2 * EE, EE);

    // ma_out = concat(ma1, ma2) @ maprojW + maprojb
    gemm(cat, mpW, mpB, maOut, NM, 2 * EE, EE, 0);
}

// round 4
// speedup vs baseline: 2.0338x; 1.7738x over previous
#include <cuda_runtime.h>
#include <cuda_bf16.h>
#include <math.h>

// Problem constants
#define BB   16
#define NO   512
#define NM   128
#define NV   64
#define EE   256
#define HH   16
#define DKK  16
#define MSS  8
#define FFF  512

// rows per encoder block (ope, veh, ma1, ma2) and cumulative offsets
#define R0 512
#define R1 64
#define R2 128
#define R3 128
#define TOTROWS (R0 + R1 + R2 + R3)   // 832

// ---------------- scratch (device globals; no allocation allowed) ------------
__device__ float g_q   [BB * TOTROWS * EE];
__device__ float g_ctx [BB * TOTROWS * EE];
__device__ float g_t1  [BB * TOTROWS * EE];
__device__ float g_out1[BB * TOTROWS * EE];
__device__ float g_h   [BB * TOTROWS * FFF];
__device__ float g_k   [4 * BB * NM * EE];
__device__ float g_v   [4 * BB * NM * EE];
__device__ float g_cat [BB * NM * (2 * EE)];
__device__ float g_Aproc   [BB * NO * NM];
__device__ float g_Aoff    [BB * NV * NM];
__device__ float g_Aprocing[BB * NM * NM];
__device__ float g_Aon     [BB * NM * NM];
__device__ float g_tt      [BB * NM * NM];
__device__ unsigned g_flags[2];          // sawFloatOne, sawOther
__device__ unsigned g_mm[2 * BB * 2];    // [tensor][b][mn,mx] as ordered uint

// ---------------- init ---------------------------------------------------------
__global__ void init_kernel() {
    int t = threadIdx.x;
    if (t < 2) g_flags[t] = 0u;
    if (t < 2 * BB * 2) g_mm[t] = (t & 1) ? 0u : 0x7F800000u;  // mn=+inf, mx=0
}

// ---------------- mask dtype sniffing ------------------------------------------
__global__ void detect_mask_kernel(const unsigned int* __restrict__ w, int nwords) {
    int f = 0, o = 0;
    for (int i = blockIdx.x * blockDim.x + threadIdx.x; i < nwords;
         i += gridDim.x * blockDim.x) {
        unsigned int x = w[i];
        if (x == 0x3F800000u) f = 1;
        else if (x != 0u && x != 1u) o = 1;
    }
    f = __syncthreads_or(f);
    o = __syncthreads_or(o);
    if (threadIdx.x == 0) {
        if (f) atomicOr(&g_flags[0], 1u);
        if (o) atomicOr(&g_flags[1], 1u);
    }
}

__device__ __forceinline__ int mask_mode() {
    unsigned f = g_flags[0], o = g_flags[1];
    return f ? 0 : (o ? 2 : 1);   // 0=float32, 1=int32, 2=uint8
}
__device__ __forceinline__ bool read_mask_m(int m, const void* p, size_t i) {
    if (m == 0) return ((const float*)p)[i] != 0.0f;
    if (m == 1) return ((const int*)p)[i] != 0;
    return ((const unsigned char*)p)[i] != 0;
}

// ---------------- adjacency kernels --------------------------------------------
__global__ void aproc_kernel(const float* __restrict__ proc, const void* maskdyn,
                             float* __restrict__ out) {
    int o = blockIdx.x, b = blockIdx.y;
    int j = threadIdx.x;            // 128 threads, one per machine
    int mode = mask_mode();
    size_t idx = ((size_t)b * NO + o) * NM + j;
    float pv = read_mask_m(mode, maskdyn, idx) ? proc[idx] : 0.0f;
    float nz = (pv == 0.0f) ? 1e30f : pv;
    int lane = j & 31, wid = j >> 5;
    float m = nz;
    #pragma unroll
    for (int off = 16; off; off >>= 1) m = fminf(m, __shfl_xor_sync(~0u, m, off));
    __shared__ float red[4];
    if (lane == 0) red[wid] = m;
    __syncthreads();
    m = fminf(fminf(red[0], red[1]), fminf(red[2], red[3]));
    out[idx] = (pv != 0.0f && pv == m) ? 1.0f : 0.0f;
}

__global__ void procing_tt_kernel(const float* __restrict__ trans, const void* maskma,
                                  float* __restrict__ outProc, float* __restrict__ outTT) {
    int i = blockIdx.x, b = blockIdx.y, j = threadIdx.x;  // 128 threads
    int mode = mask_mode();
    bool mi = read_mask_m(mode, maskma, (size_t)b * NM + i);
    bool mj = read_mask_m(mode, maskma, (size_t)b * NM + j);
    bool m2 = mi && mj;
    size_t idx = ((size_t)b * NM + i) * NM + j;
    outProc[idx] = m2 ? 0.0f : 1.0f;
    outTT[idx]   = m2 ? trans[idx] : 101.0f;
}

// min/max partial reduce over positive floats via ordered-uint atomics
__global__ void minmax_kernel(const float* __restrict__ mvp, const float* __restrict__ tt) {
    int b = blockIdx.x, s = blockIdx.y, ten = blockIdx.z;
    int S = gridDim.y;
    const float* src = ten ? tt : mvp;
    int n = ten ? (NM * NM) : (NV * NM);
    const float* ip = src + (size_t)b * n;
    int chunk = n / S, lo = s * chunk, hi = lo + chunk;
    int t = threadIdx.x, lane = t & 31, wid = t >> 5;
    float mn = 1e30f, mx = -1e30f;
    for (int i = lo + t; i < hi; i += blockDim.x) {
        float v = ip[i];
        mn = fminf(mn, v); mx = fmaxf(mx, v);
    }
    #pragma unroll
    for (int off = 16; off; off >>= 1) {
        mn = fminf(mn, __shfl_xor_sync(~0u, mn, off));
        mx = fmaxf(mx, __shfl_xor_sync(~0u, mx, off));
    }
    __shared__ float smn[8], smx[8];
    if (lane == 0) { smn[wid] = mn; smx[wid] = mx; }
    __syncthreads();
    if (t == 0) {
        int nw = blockDim.x >> 5;
        for (int i = 1; i < nw; i++) { mn = fminf(mn, smn[i]); mx = fmaxf(mx, smx[i]); }
        atomicMin(&g_mm[(ten * BB + b) * 2 + 0], __float_as_uint(mn));
        atomicMax(&g_mm[(ten * BB + b) * 2 + 1], __float_as_uint(mx));
    }
}

__global__ void invnorm_apply_kernel(const float* __restrict__ mvp, const float* __restrict__ tt,
                                     float* __restrict__ aoff, float* __restrict__ aon) {
    int b = blockIdx.x, s = blockIdx.y, ten = blockIdx.z;
    int S = gridDim.y;
    const float* src = ten ? tt : mvp;
    float* dst = ten ? aon : aoff;
    int n = ten ? (NM * NM) : (NV * NM);
    float mn = __uint_as_float(g_mm[(ten * BB + b) * 2 + 0]);
    float mx = __uint_as_float(g_mm[(ten * BB + b) * 2 + 1]);
    float inv = 1.0f / (mx - mn);
    const float* ip = src + (size_t)b * n;
    float* op = dst + (size_t)b * n;
    int chunk = n / S, lo = s * chunk, hi = lo + chunk;
    for (int i = lo + threadIdx.x; i < hi; i += blockDim.x)
        op[i] = 1.0f - (ip[i] - mn) * inv;
}

// ---------------- grouped TF32 tensor-core GEMM --------------------------------
#define GBM 128
#define GBN 64
#define GBK 32
#define MAXP 13

struct GemmProb {
    const float* A; const float* W; const float* bias; float* C;
    int R, K, N, relu, gx, gy, ctaEnd;
};
struct GemmArgs { GemmProb p[MAXP]; int np; };

__device__ __forceinline__ unsigned f2tf32(float x) {
    unsigned u;
    asm("cvt.rna.tf32.f32 %0, %1;" : "=r"(u) : "f"(x));
    return u;
}

__device__ __forceinline__ void mma_tf32(float d[4], const unsigned a[4],
                                         const unsigned bfr[2]) {
    asm volatile(
        "mma.sync.aligned.m16n8k8.row.col.f32.tf32.tf32.f32 "
        "{%0,%1,%2,%3},{%4,%5,%6,%7},{%8,%9},{%0,%1,%2,%3};\n"
        : "+f"(d[0]), "+f"(d[1]), "+f"(d[2]), "+f"(d[3])
        : "r"(a[0]), "r"(a[1]), "r"(a[2]), "r"(a[3]),
          "r"(bfr[0]), "r"(bfr[1]));
}

__global__ __launch_bounds__(256) void gemm_grouped_kernel(GemmArgs ga) {
    int cta = blockIdx.x;
    int pi = 0;
    while (cta >= ga.p[pi].ctaEnd) pi++;
    const GemmProb pr = ga.p[pi];
    int local = cta - (pi ? ga.p[pi - 1].ctaEnd : 0);
    int per = pr.gx * pr.gy;
    int bz = local / per;
    int rem = local - bz * per;
    int by = rem / pr.gx;
    int bx = rem - by * pr.gx;

    const int R = pr.R, K = pr.K, N = pr.N;
    const float* A = pr.A + (size_t)bz * R * K;
    float* C = pr.C + (size_t)bz * R * N;
    const float* W = pr.W;
    int rowBase = by * GBM;
    int colBase = bx * GBN;

    __shared__ float As[GBM][GBK + 4];
    __shared__ float Bs[GBK][GBN + 4];

    int tid = threadIdx.x;
    int warp = tid >> 5, lane = tid & 31;
    int g = lane >> 2, tig = lane & 3;
    int wm = (warp & 3) * 32;
    int wn = (warp >> 2) * 32;

    float acc[2][4][4];
    #pragma unroll
    for (int mi = 0; mi < 2; mi++)
        #pragma unroll
        for (int nj = 0; nj < 4; nj++)
            #pragma unroll
            for (int e = 0; e < 4; e++) acc[mi][nj][e] = 0.0f;

    for (int k0 = 0; k0 < K; k0 += GBK) {
        #pragma unroll
        for (int i = 0; i < 4; i++) {
            int f = tid + i * 256;
            int k4 = f & 7, m = f >> 3;
            float4 v = make_float4(0.f, 0.f, 0.f, 0.f);
            if (rowBase + m < R)
                v = *(const float4*)&A[(size_t)(rowBase + m) * K + k0 + k4 * 4];
            v.x = __uint_as_float(f2tf32(v.x));
            v.y = __uint_as_float(f2tf32(v.y));
            v.z = __uint_as_float(f2tf32(v.z));
            v.w = __uint_as_float(f2tf32(v.w));
            *(float4*)&As[m][k4 * 4] = v;
        }
        #pragma unroll
        for (int i = 0; i < 2; i++) {
            int f = tid + i * 256;
            int n4 = f & 15, k = f >> 4;
            float4 v = *(const float4*)&W[(size_t)(k0 + k) * N + colBase + n4 * 4];
            v.x = __uint_as_float(f2tf32(v.x));
            v.y = __uint_as_float(f2tf32(v.y));
            v.z = __uint_as_float(f2tf32(v.z));
            v.w = __uint_as_float(f2tf32(v.w));
            *(float4*)&Bs[k][n4 * 4] = v;
        }
        __syncthreads();

        #pragma unroll
        for (int kk = 0; kk < GBK; kk += 8) {
            unsigned afr[2][4], bfr[4][2];
            #pragma unroll
            for (int mi = 0; mi < 2; mi++) {
                int r = wm + mi * 16 + g;
                afr[mi][0] = __float_as_uint(As[r][kk + tig]);
                afr[mi][1] = __float_as_uint(As[r + 8][kk + tig]);
                afr[mi][2] = __float_as_uint(As[r][kk + tig + 4]);
                afr[mi][3] = __float_as_uint(As[r + 8][kk + tig + 4]);
            }
            #pragma unroll
            for (int nj = 0; nj < 4; nj++) {
                int c = wn + nj * 8 + g;
                bfr[nj][0] = __float_as_uint(Bs[kk + tig][c]);
                bfr[nj][1] = __float_as_uint(Bs[kk + tig + 4][c]);
            }
            #pragma unroll
            for (int mi = 0; mi < 2; mi++)
                #pragma unroll
                for (int nj = 0; nj < 4; nj++)
                    mma_tf32(acc[mi][nj], afr[mi], bfr[nj]);
        }
        __syncthreads();
    }

    #pragma unroll
    for (int mi = 0; mi < 2; mi++) {
        #pragma unroll
        for (int nj = 0; nj < 4; nj++) {
            int r0 = rowBase + wm + mi * 16 + g;
            int c0 = colBase + wn + nj * 8 + tig * 2;
            float b0 = 0.f, b1 = 0.f;
            if (pr.bias) { b0 = pr.bias[c0]; b1 = pr.bias[c0 + 1]; }
            float v0 = acc[mi][nj][0] + b0, v1 = acc[mi][nj][1] + b1;
            float v2 = acc[mi][nj][2] + b0, v3 = acc[mi][nj][3] + b1;
            if (pr.relu) {
                v0 = fmaxf(v0, 0.f); v1 = fmaxf(v1, 0.f);
                v2 = fmaxf(v2, 0.f); v3 = fmaxf(v3, 0.f);
            }
            if (r0 < R) {
                float2 p = make_float2(v0, v1);
                *(float2*)&C[(size_t)r0 * N + c0] = p;
            }
            if (r0 + 8 < R) {
                float2 p = make_float2(v2, v3);
                *(float2*)&C[(size_t)(r0 + 8) * N + c0] = p;
            }
        }
    }
}

// ---------------- grouped fused attention --------------------------------------
struct AttnProb {
    const float* Q; const float* Kp; const float* Vp; const float* cost; float* ctx;
    const float* mw1; const float* mb1; const float* mw2; const float* mb2;
    int R, unitEnd;
};
struct AttnArgs { AttnProb p[4]; int np; };

__global__ __launch_bounds__(128) void attn_grouped_kernel(AttnArgs aa) {
    const int C = 128;
    int flat = blockIdx.x;
    int pi = 0;
    while (flat >= aa.p[pi].unitEnd) pi++;
    const AttnProb pr = aa.p[pi];
    int u = flat - (pi ? aa.p[pi - 1].unitEnd : 0);
    int rowTile = u / (BB * HH);
    int bh = u - rowTile * (BB * HH);
    int b = bh >> 4, h = bh & 15;
    int R = pr.R;
    int r0 = rowTile * 32;
    int tid = threadIdx.x;
    int lane = tid & 31, wid = tid >> 5;

    __shared__ float Ks[128][17], Vs[128][17];
    __shared__ float qs[16], psh[128], red[4], part[8][16];
    __shared__ float w1d[8], w1c[8], b1s[8], w2s[8], b2s[1];

    if (tid < 8) {
        w1d[tid] = pr.mw1[h * 16 + tid];
        w1c[tid] = pr.mw1[h * 16 + 8 + tid];
        b1s[tid] = pr.mb1[h * 8 + tid];
        w2s[tid] = pr.mw2[h * 8 + tid];
    }
    if (tid == 0) b2s[0] = pr.mb2[h];

    for (int idx = tid; idx < C * 16; idx += 128) {
        int c = idx >> 4, d = idx & 15;
        size_t gg = ((size_t)b * C + c) * EE + h * 16 + d;
        Ks[c][d] = pr.Kp[gg];
        Vs[c][d] = pr.Vp[gg];
    }
    __syncthreads();

    for (int r = r0; r < r0 + 32; r++) {
        if (tid < 16) qs[tid] = pr.Q[((size_t)b * R + r) * EE + h * 16 + tid];
        __syncthreads();

        int c = tid;
        float dot = 0.0f;
        #pragma unroll
        for (int d = 0; d < 16; d++) dot += qs[d] * Ks[c][d];
        dot *= 0.25f;
        float cv = pr.cost[((size_t)b * R + r) * C + c];
        float sc = b2s[0];
        #pragma unroll
        for (int s = 0; s < 8; s++) {
            float t = dot * w1d[s] + cv * w1c[s] + b1s[s];
            sc += fmaxf(t, 0.0f) * w2s[s];
        }
        float m = sc;
        #pragma unroll
        for (int off = 16; off; off >>= 1) m = fmaxf(m, __shfl_xor_sync(~0u, m, off));
        if (lane == 0) red[wid] = m;
        __syncthreads();
        m = fmaxf(fmaxf(red[0], red[1]), fmaxf(red[2], red[3]));
        float p = expf(sc - m);
        __syncthreads();
        float ssum = p;
        #pragma unroll
        for (int off = 16; off; off >>= 1) ssum += __shfl_xor_sync(~0u, ssum, off);
        if (lane == 0) red[wid] = ssum;
        __syncthreads();
        ssum = red[0] + red[1] + red[2] + red[3];
        psh[tid] = p / ssum;
        __syncthreads();

        int d = tid & 15, gq = tid >> 4;
        float acc = 0.0f;
        #pragma unroll
        for (int i = 0; i < 16; i++) {
            int cc = gq * 16 + i;
            acc += psh[cc] * Vs[cc][d];
        }
        part[gq][d] = acc;
        __syncthreads();
        if (tid < 16) {
            float s2 = 0.0f;
            #pragma unroll
            for (int ggq = 0; ggq < 8; ggq++) s2 += part[ggq][tid];
            pr.ctx[((size_t)b * R + r) * EE + h * 16 + tid] = s2;
        }
        __syncthreads();
    }
}

// ---------------- grouped residual-add + layernorm ------------------------------
struct LnProb {
    const float* x; const float* res; float* out;
    int stride, colOff, unitEnd;
};
struct LnArgs { LnProb p[4]; int np; };

__global__ __launch_bounds__(256) void add_ln_grouped_kernel(LnArgs la) {
    int flat = blockIdx.x;
    int pi = 0;
    while (flat >= la.p[pi].unitEnd) pi++;
    const LnProb pr = la.p[pi];
    int row = flat - (pi ? la.p[pi - 1].unitEnd : 0);

    int t = threadIdx.x, lane = t & 31, wid = t >> 5;
    float v = pr.x[(size_t)row * EE + t] + pr.res[(size_t)row * EE + t];
    __shared__ float red[8];
    float s = v;
    #pragma unroll
    for (int off = 16; off; off >>= 1) s += __shfl_xor_sync(~0u, s, off);
    if (lane == 0) red[wid] = s;
    __syncthreads();
    s = 0.0f;
    #pragma unroll
    for (int i = 0; i < 8; i++) s += red[i];
    float mean = s * (1.0f / EE);
    float d = v - mean;
    __syncthreads();
    float s2 = d * d;
    #pragma unroll
    for (int off = 16; off; off >>= 1) s2 += __shfl_xor_sync(~0u, s2, off);
    if (lane == 0) red[wid] = s2;
    __syncthreads();
    s2 = 0.0f;
    #pragma unroll
    for (int i = 0; i < 8; i++) s2 += red[i];
    float var = s2 * (1.0f / EE);
    float rstd = rsqrtf(var + 1e-5f);
    pr.out[(size_t)row * pr.stride + pr.colOff + t] = d * rstd;
}

// ---------------- host orchestration --------------------------------------------
static float* symaddr_f(const void* sym) {
    void* p = nullptr;
    cudaGetSymbolAddress(&p, sym);
    return (float*)p;
}

extern "C" void kernel_launch(void* const* d_in, const int* in_sizes, int n_in,
                              void* d_out, int out_size) {
    const float* rowEmb[4];
    rowEmb[0] = (const float*)d_in[0];   // ope
    const float* maEmb = (const float*)d_in[1];
    rowEmb[1] = (const float*)d_in[2];   // veh
    rowEmb[2] = maEmb;
    rowEmb[3] = maEmb;
    const float* proc  = (const float*)d_in[3];
    const float* trans = (const float*)d_in[5];
    const float* mvp   = (const float*)d_in[6];
    const void*  mdyn  = d_in[7];
    const void*  mma   = d_in[8];
    const float* Wq = (const float*)d_in[9];
    const float* Wk = (const float*)d_in[10];
    const float* Wv = (const float*)d_in[11];
    const float* Wo = (const float*)d_in[12];
    const float* mixW1 = (const float*)d_in[13];
    const float* mixb1 = (const float*)d_in[14];
    const float* mixW2 = (const float*)d_in[15];
    const float* mixb2 = (const float*)d_in[16];
    const float* ffW1 = (const float*)d_in[17];
    const float* ffb1 = (const float*)d_in[18];
    const float* ffW2 = (const float*)d_in[19];
    const float* ffb2 = (const float*)d_in[20];
    const float* mpW = (const float*)d_in[21];
    const float* mpB = (const float*)d_in[22];

    float* q    = symaddr_f((const void*)g_q);
    float* ctx  = symaddr_f((const void*)g_ctx);
    float* t1   = symaddr_f((const void*)g_t1);
    float* out1 = symaddr_f((const void*)g_out1);
    float* hbuf = symaddr_f((const void*)g_h);
    float* kbuf = symaddr_f((const void*)g_k);
    float* vbuf = symaddr_f((const void*)g_v);
    float* cat  = symaddr_f((const void*)g_cat);
    float* aproc = symaddr_f((const void*)g_Aproc);
    float* aoff  = symaddr_f((const void*)g_Aoff);
    float* aping = symaddr_f((const void*)g_Aprocing);
    float* aon   = symaddr_f((const void*)g_Aon);
    float* ttb   = symaddr_f((const void*)g_tt);

    const int Rv[4] = {R0, R1, R2, R3};
    const int rowOff[4] = {0, R0, R0 + R1, R0 + R1 + R2};

    // per-block scratch bases
    float *qB[4], *ctxB[4], *t1B[4], *out1B[4], *hB[4], *kB[4], *vB[4];
    for (int i = 0; i < 4; i++) {
        qB[i]    = q    + (size_t)BB * rowOff[i] * EE;
        ctxB[i]  = ctx  + (size_t)BB * rowOff[i] * EE;
        t1B[i]   = t1   + (size_t)BB * rowOff[i] * EE;
        out1B[i] = out1 + (size_t)BB * rowOff[i] * EE;
        hB[i]    = hbuf + (size_t)BB * rowOff[i] * FFF;
        kB[i]    = kbuf + (size_t)i * BB * NM * EE;
        vB[i]    = vbuf + (size_t)i * BB * NM * EE;
    }

    // ---- preprocessing ----
    init_kernel<<<1, 64>>>();
    detect_mask_kernel<<<64, 256>>>((const unsigned int*)mdyn, (BB * NO * NM) / 4);
    aproc_kernel<<<dim3(NO, BB), NM>>>(proc, mdyn, aproc);
    procing_tt_kernel<<<dim3(NM, BB), NM>>>(trans, mma, aping, ttb);
    minmax_kernel<<<dim3(BB, 4, 2), 256>>>(mvp, ttb);
    invnorm_apply_kernel<<<dim3(BB, 4, 2), 256>>>(mvp, ttb, aoff, aon);

    float* outF = (float*)d_out;
    float* opeOut = outF;
    float* maOut  = outF + (size_t)BB * NO * EE;
    float* vehOut = maOut + (size_t)BB * NM * EE;

    auto addGemm = [](GemmArgs& ga, const float* A, const float* W, const float* bias,
                      float* C, int R, int K, int N, int relu) {
        GemmProb& pr = ga.p[ga.np];
        pr.A = A; pr.W = W; pr.bias = bias; pr.C = C;
        pr.R = R; pr.K = K; pr.N = N; pr.relu = relu;
        pr.gx = N / GBN; pr.gy = (R + GBM - 1) / GBM;
        int prev = ga.np ? ga.p[ga.np - 1].ctaEnd : 0;
        pr.ctaEnd = prev + pr.gx * pr.gy * BB;
        ga.np++;
    };
    auto runGemm = [](GemmArgs& ga) {
        gemm_grouped_kernel<<<ga.p[ga.np - 1].ctaEnd, 256>>>(ga);
    };

    // ---- phase 1: QKV for all 4 blocks ----
    {
        GemmArgs ga; ga.np = 0;
        for (int i = 0; i < 4; i++) {
            addGemm(ga, rowEmb[i], Wq + (size_t)i * EE * EE, nullptr, qB[i], Rv[i], EE, EE, 0);
            addGemm(ga, maEmb,     Wk + (size_t)i * EE * EE, nullptr, kB[i], NM,    EE, EE, 0);
            addGemm(ga, maEmb,     Wv + (size_t)i * EE * EE, nullptr, vB[i], NM,    EE, EE, 0);
        }
        runGemm(ga);
    }

    // ---- phase 2: attention for all 4 blocks ----
    {
        const float* costs[4] = {aproc, aoff, aping, aon};
        AttnArgs aa; aa.np = 4;
        int acc = 0;
        for (int i = 0; i < 4; i++) {
            AttnProb& pr = aa.p[i];
            pr.Q = qB[i]; pr.Kp = kB[i]; pr.Vp = vB[i];
            pr.cost = costs[i]; pr.ctx = ctxB[i];
            pr.mw1 = mixW1 + (size_t)i * HH * 2 * MSS;
            pr.mb1 = mixb1 + (size_t)i * HH * MSS;
            pr.mw2 = mixW2 + (size_t)i * HH * MSS;
            pr.mb2 = mixb2 + (size_t)i * HH;
            pr.R = Rv[i];
            acc += (Rv[i] / 32) * BB * HH;
            pr.unitEnd = acc;
        }
        attn_grouped_kernel<<<acc, 128>>>(aa);
    }

    // ---- phase 3: O projection ----
    {
        GemmArgs ga; ga.np = 0;
        for (int i = 0; i < 4; i++)
            addGemm(ga, ctxB[i], Wo + (size_t)i * EE * EE, nullptr, t1B[i], Rv[i], EE, EE, 0);
        runGemm(ga);
    }

    // ---- phase 4: add + LN (-> out1) ----
    {
        LnArgs la; la.np = 4;
        int acc = 0;
        for (int i = 0; i < 4; i++) {
            LnProb& pr = la.p[i];
            pr.x = t1B[i]; pr.res = rowEmb[i]; pr.out = out1B[i];
            pr.stride = EE; pr.colOff = 0;
            acc += BB * Rv[i];
            pr.unitEnd = acc;
        }
        add_ln_grouped_kernel<<<acc, 256>>>(la);
    }

    // ---- phase 5: FFN up (relu) ----
    {
        GemmArgs ga; ga.np = 0;
        for (int i = 0; i < 4; i++)
            addGemm(ga, out1B[i], ffW1 + (size_t)i * EE * FFF, ffb1 + (size_t)i * FFF,
                    hB[i], Rv[i], EE, FFF, 1);
        runGemm(ga);
    }

    // ---- phase 6: FFN down ----
    {
        GemmArgs ga; ga.np = 0;
        for (int i = 0; i < 4; i++)
            addGemm(ga, hB[i], ffW2 + (size_t)i * FFF * EE, ffb2 + (size_t)i * EE,
                    t1B[i], Rv[i], FFF, EE, 0);
        runGemm(ga);
    }

    // ---- phase 7: add + LN (-> final outputs / cat) ----
    {
        LnArgs la; la.np = 4;
        float* dsts[4]    = {opeOut, vehOut, cat, cat};
        int strides[4]    = {EE, EE, 2 * EE, 2 * EE};
        int colOffs[4]    = {0, 0, 0, EE};
        int acc = 0;
        for (int i = 0; i < 4; i++) {
            LnProb& pr = la.p[i];
            pr.x = t1B[i]; pr.res = out1B[i]; pr.out = dsts[i];
            pr.stride = strides[i]; pr.colOff = colOffs[i];
            acc += BB * Rv[i];
            pr.unitEnd = acc;
        }
        add_ln_grouped_kernel<<<acc, 256>>>(la);
    }

    // ---- phase 8: final machine projection ----
    {
        GemmArgs ga; ga.np = 0;
        addGemm(ga, cat, mpW, mpB, maOut, NM, 2 * EE, EE, 0);
        runGemm(ga);
    }
}

// round 6
// speedup vs baseline: 3.8979x; 1.9166x over previous
#include <cuda_runtime.h>
#include <stdint.h>
#include <math.h>

// Problem constants
#define BB   16
#define NO   512
#define NM   128
#define NV   64
#define EE   256
#define HH   16
#define MSS  8
#define FFF  512

#define R0 512
#define R1 64
#define R2 128
#define R3 128
#define TOTROWS (R0 + R1 + R2 + R3)   // 832

// ---------------- scratch (device globals) -----------------------------------
__device__ float g_q   [BB * TOTROWS * EE];
__device__ float g_ctx [BB * TOTROWS * EE];
__device__ float g_out1[BB * TOTROWS * EE];
__device__ float g_h   [BB * TOTROWS * FFF];
__device__ float g_k   [4 * BB * NM * EE];
__device__ float g_v   [4 * BB * NM * EE];
__device__ float g_cat [BB * NM * (2 * EE)];
__device__ float g_Aproc   [BB * NO * NM];
__device__ float g_Aoff    [BB * NV * NM];
__device__ float g_Aprocing[BB * NM * NM];
__device__ float g_Aon     [BB * NM * NM];
__device__ float g_tt      [BB * NM * NM];
__device__ unsigned g_flags[2];
__device__ unsigned g_mm[2 * BB * 2];

// ---------------- init --------------------------------------------------------
__global__ void init_kernel() {
    int t = threadIdx.x;
    if (t < 2) g_flags[t] = 0u;
    if (t < 2 * BB * 2) g_mm[t] = (t & 1) ? 0u : 0x7F800000u;
}

// ---------------- mask dtype sniffing -----------------------------------------
__global__ void detect_mask_kernel(const unsigned int* __restrict__ w, int nwords) {
    int f = 0, o = 0;
    for (int i = blockIdx.x * blockDim.x + threadIdx.x; i < nwords;
         i += gridDim.x * blockDim.x) {
        unsigned int x = w[i];
        if (x == 0x3F800000u) f = 1;
        else if (x != 0u && x != 1u) o = 1;
    }
    f = __syncthreads_or(f);
    o = __syncthreads_or(o);
    if (threadIdx.x == 0) {
        if (f) atomicOr(&g_flags[0], 1u);
        if (o) atomicOr(&g_flags[1], 1u);
    }
}

__device__ __forceinline__ int mask_mode() {
    unsigned f = g_flags[0], o = g_flags[1];
    return f ? 0 : (o ? 2 : 1);
}
__device__ __forceinline__ bool read_mask_m(int m, const void* p, size_t i) {
    if (m == 0) return ((const float*)p)[i] != 0.0f;
    if (m == 1) return ((const int*)p)[i] != 0;
    return ((const unsigned char*)p)[i] != 0;
}

// ---------------- adjacency kernels -------------------------------------------
__global__ void aproc_kernel(const float* __restrict__ proc, const void* maskdyn,
                             float* __restrict__ out) {
    int o = blockIdx.x, b = blockIdx.y;
    int j = threadIdx.x;
    int mode = mask_mode();
    size_t idx = ((size_t)b * NO + o) * NM + j;
    float pv = read_mask_m(mode, maskdyn, idx) ? proc[idx] : 0.0f;
    float nz = (pv == 0.0f) ? 1e30f : pv;
    int lane = j & 31, wid = j >> 5;
    float m = nz;
    #pragma unroll
    for (int off = 16; off; off >>= 1) m = fminf(m, __shfl_xor_sync(~0u, m, off));
    __shared__ float red[4];
    if (lane == 0) red[wid] = m;
    __syncthreads();
    m = fminf(fminf(red[0], red[1]), fminf(red[2], red[3]));
    out[idx] = (pv != 0.0f && pv == m) ? 1.0f : 0.0f;
}

__global__ void procing_tt_kernel(const float* __restrict__ trans, const void* maskma,
                                  float* __restrict__ outProc, float* __restrict__ outTT) {
    int i = blockIdx.x, b = blockIdx.y, j = threadIdx.x;
    int mode = mask_mode();
    bool mi = read_mask_m(mode, maskma, (size_t)b * NM + i);
    bool mj = read_mask_m(mode, maskma, (size_t)b * NM + j);
    bool m2 = mi && mj;
    size_t idx = ((size_t)b * NM + i) * NM + j;
    outProc[idx] = m2 ? 0.0f : 1.0f;
    outTT[idx]   = m2 ? trans[idx] : 101.0f;
}

__global__ void minmax_kernel(const float* __restrict__ mvp, const float* __restrict__ tt) {
    int b = blockIdx.x, s = blockIdx.y, ten = blockIdx.z;
    int S = gridDim.y;
    const float* src = ten ? tt : mvp;
    int n = ten ? (NM * NM) : (NV * NM);
    const float* ip = src + (size_t)b * n;
    int chunk = n / S, lo = s * chunk, hi = lo + chunk;
    int t = threadIdx.x, lane = t & 31, wid = t >> 5;
    float mn = 1e30f, mx = -1e30f;
    for (int i = lo + t; i < hi; i += blockDim.x) {
        float v = ip[i];
        mn = fminf(mn, v); mx = fmaxf(mx, v);
    }
    #pragma unroll
    for (int off = 16; off; off >>= 1) {
        mn = fminf(mn, __shfl_xor_sync(~0u, mn, off));
        mx = fmaxf(mx, __shfl_xor_sync(~0u, mx, off));
    }
    __shared__ float smn[8], smx[8];
    if (lane == 0) { smn[wid] = mn; smx[wid] = mx; }
    __syncthreads();
    if (t == 0) {
        int nw = blockDim.x >> 5;
        for (int i = 1; i < nw; i++) { mn = fminf(mn, smn[i]); mx = fmaxf(mx, smx[i]); }
        atomicMin(&g_mm[(ten * BB + b) * 2 + 0], __float_as_uint(mn));
        atomicMax(&g_mm[(ten * BB + b) * 2 + 1], __float_as_uint(mx));
    }
}

__global__ void invnorm_apply_kernel(const float* __restrict__ mvp, const float* __restrict__ tt,
                                     float* __restrict__ aoff, float* __restrict__ aon) {
    int b = blockIdx.x, s = blockIdx.y, ten = blockIdx.z;
    int S = gridDim.y;
    const float* src = ten ? tt : mvp;
    float* dst = ten ? aon : aoff;
    int n = ten ? (NM * NM) : (NV * NM);
    float mn = __uint_as_float(g_mm[(ten * BB + b) * 2 + 0]);
    float mx = __uint_as_float(g_mm[(ten * BB + b) * 2 + 1]);
    float inv = 1.0f / (mx - mn);
    const float* ip = src + (size_t)b * n;
    float* op = dst + (size_t)b * n;
    int chunk = n / S, lo = s * chunk, hi = lo + chunk;
    for (int i = lo + threadIdx.x; i < hi; i += blockDim.x)
        op[i] = 1.0f - (ip[i] - mn) * inv;
}

// ---------------- grouped TF32 GEMM, 64x256 tile, cp.async double buffer ------
#define TBM 64
#define TBN 256
#define TBK 32
#define APAD 36
#define BPAD 264
#define ASZ (TBM * APAD)            // 2304 floats
#define BSZ (TBK * BPAD)            // 8448 floats
#define SMEM_FLOATS (2 * ASZ + 2 * BSZ)   // 21504 floats = 86016 B
#define MAXP 12

struct GemmProb {
    const float* A; const float* W; const float* bias; const float* res; float* C;
    int R, K, N, relu, stride, colOff, gx, gy, ctaEnd;
};
struct GemmArgs { GemmProb p[MAXP]; int np; };

__device__ __forceinline__ unsigned f2tf32(float x) {
    unsigned u;
    asm("cvt.rna.tf32.f32 %0, %1;" : "=r"(u) : "f"(x));
    return u;
}
__device__ __forceinline__ void mma_tf32(float d[4], const unsigned a[4],
                                         const unsigned b[2]) {
    asm volatile(
        "mma.sync.aligned.m16n8k8.row.col.f32.tf32.tf32.f32 "
        "{%0,%1,%2,%3},{%4,%5,%6,%7},{%8,%9},{%0,%1,%2,%3};\n"
        : "+f"(d[0]), "+f"(d[1]), "+f"(d[2]), "+f"(d[3])
        : "r"(a[0]), "r"(a[1]), "r"(a[2]), "r"(a[3]), "r"(b[0]), "r"(b[1]));
}
__device__ __forceinline__ void cp16(uint32_t dst, const float* src) {
    asm volatile("cp.async.cg.shared.global [%0], [%1], 16;\n" :: "r"(dst), "l"(src));
}

__global__ __launch_bounds__(256) void gemm_grouped_kernel(GemmArgs ga) {
    extern __shared__ float sm[];
    float* AsB[2] = { sm, sm + ASZ };
    float* BsB[2] = { sm + 2 * ASZ, sm + 2 * ASZ + BSZ };

    int cta = blockIdx.x;
    int pi = 0;
    while (cta >= ga.p[pi].ctaEnd) pi++;
    const GemmProb pr = ga.p[pi];
    int local = cta - (pi ? ga.p[pi - 1].ctaEnd : 0);
    int per = pr.gx * pr.gy;
    int bz = local / per;
    int rem = local - bz * per;
    int by = rem / pr.gx;
    int bx = rem - by * pr.gx;

    const int K = pr.K, N = pr.N, stride = pr.stride;
    const float* A = pr.A + (size_t)bz * pr.R * K;
    const float* W = pr.W;
    float* C = pr.C + (size_t)bz * pr.R * stride;
    const float* res = pr.res ? pr.res + (size_t)bz * pr.R * EE : (const float*)0;
    int rowBase = by * TBM;
    int colBase = bx * TBN;

    int tid = threadIdx.x;
    int warp = tid >> 5, lane = tid & 31;
    int g = lane >> 2, tig = lane & 3;
    int wm = warp & 1;       // 2 warps along M (32 rows each)
    int wn = warp >> 1;      // 4 warps along N (64 cols each)

    float acc[2][8][4];
    #pragma unroll
    for (int mi = 0; mi < 2; mi++)
        #pragma unroll
        for (int nj = 0; nj < 8; nj++)
            #pragma unroll
            for (int e = 0; e < 4; e++) acc[mi][nj][e] = 0.0f;

    auto loadTiles = [&](int buf, int k0) {
        #pragma unroll
        for (int i = 0; i < 2; i++) {
            int f = tid + i * 256;
            int m = f >> 3, k4 = f & 7;
            uint32_t dst = (uint32_t)__cvta_generic_to_shared(AsB[buf] + m * APAD + k4 * 4);
            cp16(dst, A + (size_t)(rowBase + m) * K + k0 + k4 * 4);
        }
        #pragma unroll
        for (int i = 0; i < 8; i++) {
            int f = tid + i * 256;
            int k = f >> 6, n4 = f & 63;
            uint32_t dst = (uint32_t)__cvta_generic_to_shared(BsB[buf] + k * BPAD + n4 * 4);
            cp16(dst, W + (size_t)(k0 + k) * N + colBase + n4 * 4);
        }
    };

    int iters = K / TBK;
    loadTiles(0, 0);
    asm volatile("cp.async.commit_group;\n");
    for (int it = 0; it < iters; it++) {
        int buf = it & 1;
        if (it + 1 < iters) loadTiles(buf ^ 1, (it + 1) * TBK);
        asm volatile("cp.async.commit_group;\n");
        asm volatile("cp.async.wait_group 1;\n");
        __syncthreads();
        const float* As = AsB[buf];
        const float* Bs = BsB[buf];
        #pragma unroll
        for (int kk = 0; kk < TBK; kk += 8) {
            unsigned afr[2][4], bfr[8][2];
            #pragma unroll
            for (int mi = 0; mi < 2; mi++) {
                int r = wm * 32 + mi * 16 + g;
                afr[mi][0] = f2tf32(As[r * APAD + kk + tig]);
                afr[mi][1] = f2tf32(As[(r + 8) * APAD + kk + tig]);
                afr[mi][2] = f2tf32(As[r * APAD + kk + tig + 4]);
                afr[mi][3] = f2tf32(As[(r + 8) * APAD + kk + tig + 4]);
            }
            #pragma unroll
            for (int nj = 0; nj < 8; nj++) {
                int c = wn * 64 + nj * 8 + g;
                bfr[nj][0] = f2tf32(Bs[(kk + tig) * BPAD + c]);
                bfr[nj][1] = f2tf32(Bs[(kk + tig + 4) * BPAD + c]);
            }
            #pragma unroll
            for (int mi = 0; mi < 2; mi++)
                #pragma unroll
                for (int nj = 0; nj < 8; nj++)
                    mma_tf32(acc[mi][nj], afr[mi], bfr[nj]);
        }
        __syncthreads();
    }

    if (res) {
        // fused add-residual + LayerNorm epilogue (N == EE == 256, colBase == 0)
        float* sred1 = sm;          // [64][4]
        float* sred2 = sm + 256;
        float s1[2][2], s2[2][2];
        #pragma unroll
        for (int mi = 0; mi < 2; mi++) {
            #pragma unroll
            for (int h2 = 0; h2 < 2; h2++) {
                int rloc = wm * 32 + mi * 16 + g + h2 * 8;
                int rowG = rowBase + rloc;
                float a = 0.f, bq = 0.f;
                #pragma unroll
                for (int nj = 0; nj < 8; nj++) {
                    int c = wn * 64 + nj * 8 + tig * 2;
                    float v0 = acc[mi][nj][h2 * 2], v1 = acc[mi][nj][h2 * 2 + 1];
                    if (pr.bias) { v0 += pr.bias[c]; v1 += pr.bias[c + 1]; }
                    float2 rv = *(const float2*)&res[(size_t)rowG * EE + c];
                    v0 += rv.x; v1 += rv.y;
                    acc[mi][nj][h2 * 2] = v0; acc[mi][nj][h2 * 2 + 1] = v1;
                    a += v0 + v1; bq += v0 * v0 + v1 * v1;
                }
                s1[mi][h2] = a; s2[mi][h2] = bq;
            }
        }
        #pragma unroll
        for (int mi = 0; mi < 2; mi++)
            #pragma unroll
            for (int h2 = 0; h2 < 2; h2++) {
                s1[mi][h2] += __shfl_xor_sync(~0u, s1[mi][h2], 1);
                s1[mi][h2] += __shfl_xor_sync(~0u, s1[mi][h2], 2);
                s2[mi][h2] += __shfl_xor_sync(~0u, s2[mi][h2], 1);
                s2[mi][h2] += __shfl_xor_sync(~0u, s2[mi][h2], 2);
            }
        if (tig == 0) {
            #pragma unroll
            for (int mi = 0; mi < 2; mi++)
                #pragma unroll
                for (int h2 = 0; h2 < 2; h2++) {
                    int rloc = wm * 32 + mi * 16 + g + h2 * 8;
                    sred1[rloc * 4 + wn] = s1[mi][h2];
                    sred2[rloc * 4 + wn] = s2[mi][h2];
                }
        }
        __syncthreads();
        #pragma unroll
        for (int mi = 0; mi < 2; mi++) {
            #pragma unroll
            for (int h2 = 0; h2 < 2; h2++) {
                int rloc = wm * 32 + mi * 16 + g + h2 * 8;
                float t1 = sred1[rloc * 4 + 0] + sred1[rloc * 4 + 1]
                         + sred1[rloc * 4 + 2] + sred1[rloc * 4 + 3];
                float t2 = sred2[rloc * 4 + 0] + sred2[rloc * 4 + 1]
                         + sred2[rloc * 4 + 2] + sred2[rloc * 4 + 3];
                float mean = t1 * (1.0f / 256.0f);
                float var = t2 * (1.0f / 256.0f) - mean * mean;
                float rstd = rsqrtf(var + 1e-5f);
                size_t base = (size_t)(rowBase + rloc) * stride + pr.colOff;
                #pragma unroll
                for (int nj = 0; nj < 8; nj++) {
                    int c = wn * 64 + nj * 8 + tig * 2;
                    float v0 = (acc[mi][nj][h2 * 2] - mean) * rstd;
                    float v1 = (acc[mi][nj][h2 * 2 + 1] - mean) * rstd;
                    *(float2*)&C[base + c] = make_float2(v0, v1);
                }
            }
        }
    } else {
        #pragma unroll
        for (int mi = 0; mi < 2; mi++) {
            #pragma unroll
            for (int h2 = 0; h2 < 2; h2++) {
                int rloc = wm * 32 + mi * 16 + g + h2 * 8;
                size_t base = (size_t)(rowBase + rloc) * stride + pr.colOff;
                #pragma unroll
                for (int nj = 0; nj < 8; nj++) {
                    int cl = wn * 64 + nj * 8 + tig * 2;
                    int c = colBase + cl;
                    float v0 = acc[mi][nj][h2 * 2], v1 = acc[mi][nj][h2 * 2 + 1];
                    if (pr.bias) { v0 += pr.bias[c]; v1 += pr.bias[c + 1]; }
                    if (pr.relu) { v0 = fmaxf(v0, 0.f); v1 = fmaxf(v1, 0.f); }
                    *(float2*)&C[base + c] = make_float2(v0, v1);
                }
            }
        }
    }
}

// ---------------- grouped fused attention (warp-per-row) ----------------------
struct AttnProb {
    const float* Q; const float* Kp; const float* Vp; const float* cost; float* ctx;
    const float* mw1; const float* mb1; const float* mw2; const float* mb2;
    int R, unitEnd;
};
struct AttnArgs { AttnProb p[4]; int np; };

__global__ __launch_bounds__(256) void attn_grouped_kernel(AttnArgs aa) {
    const int C = 128;
    int flat = blockIdx.x;
    int pi = 0;
    while (flat >= aa.p[pi].unitEnd) pi++;
    const AttnProb pr = aa.p[pi];
    int u = flat - (pi ? aa.p[pi - 1].unitEnd : 0);
    int rowTile = u / (BB * HH);
    int bh = u - rowTile * (BB * HH);
    int b = bh >> 4, h = bh & 15;
    int R = pr.R;
    int r0 = rowTile * 32;
    int tid = threadIdx.x;
    int w = tid >> 5, lane = tid & 31;

    __shared__ float Ks[128][17], Vs[128][17];
    __shared__ float psh[8][128];
    __shared__ float w1d[8], w1c[8], b1s[8], w2s[8], b2s[1];

    if (tid < 8) {
        w1d[tid] = pr.mw1[h * 16 + tid];
        w1c[tid] = pr.mw1[h * 16 + 8 + tid];
        b1s[tid] = pr.mb1[h * 8 + tid];
        w2s[tid] = pr.mw2[h * 8 + tid];
    }
    if (tid == 0) b2s[0] = pr.mb2[h];

    for (int idx = tid; idx < C * 16; idx += 256) {
        int c = idx >> 4, d = idx & 15;
        size_t gg = ((size_t)b * C + c) * EE + h * 16 + d;
        Ks[c][d] = pr.Kp[gg];
        Vs[c][d] = pr.Vp[gg];
    }
    __syncthreads();

    #pragma unroll
    for (int rr = 0; rr < 4; rr++) {
        int r = r0 + w * 4 + rr;
        float qv = pr.Q[((size_t)b * R + r) * EE + h * 16 + (lane & 15)];
        float dot[4] = {0.f, 0.f, 0.f, 0.f};
        #pragma unroll
        for (int d = 0; d < 16; d++) {
            float qd = __shfl_sync(~0u, qv, d);
            #pragma unroll
            for (int j = 0; j < 4; j++) dot[j] += qd * Ks[j * 32 + lane][d];
        }
        float sc[4];
        #pragma unroll
        for (int j = 0; j < 4; j++) {
            float dj = dot[j] * 0.25f;
            float cv = pr.cost[((size_t)b * R + r) * C + j * 32 + lane];
            float s = b2s[0];
            #pragma unroll
            for (int k = 0; k < 8; k++) {
                float t = dj * w1d[k] + cv * w1c[k] + b1s[k];
                s += fmaxf(t, 0.0f) * w2s[k];
            }
            sc[j] = s;
        }
        float m = fmaxf(fmaxf(sc[0], sc[1]), fmaxf(sc[2], sc[3]));
        #pragma unroll
        for (int off = 16; off; off >>= 1) m = fmaxf(m, __shfl_xor_sync(~0u, m, off));
        float p[4], ssum = 0.f;
        #pragma unroll
        for (int j = 0; j < 4; j++) { p[j] = expf(sc[j] - m); ssum += p[j]; }
        #pragma unroll
        for (int off = 16; off; off >>= 1) ssum += __shfl_xor_sync(~0u, ssum, off);
        float inv = 1.0f / ssum;
        #pragma unroll
        for (int j = 0; j < 4; j++) psh[w][j * 32 + lane] = p[j] * inv;
        __syncwarp();

        int d = lane & 15, half = lane >> 4;
        float acc = 0.f;
        #pragma unroll
        for (int i = 0; i < 64; i++) {
            int c = half * 64 + i;
            acc += psh[w][c] * Vs[c][d];
        }
        acc += __shfl_xor_sync(~0u, acc, 16);
        if (lane < 16)
            pr.ctx[((size_t)b * R + r) * EE + h * 16 + lane] = acc;
        __syncwarp();
    }
}

// ---------------- host orchestration ------------------------------------------
static float* symaddr_f(const void* sym) {
    void* p = nullptr;
    cudaGetSymbolAddress(&p, sym);
    return (float*)p;
}

extern "C" void kernel_launch(void* const* d_in, const int* in_sizes, int n_in,
                              void* d_out, int out_size) {
    const float* rowEmb[4];
    rowEmb[0] = (const float*)d_in[0];
    const float* maEmb = (const float*)d_in[1];
    rowEmb[1] = (const float*)d_in[2];
    rowEmb[2] = maEmb;
    rowEmb[3] = maEmb;
    const float* proc  = (const float*)d_in[3];
    const float* trans = (const float*)d_in[5];
    const float* mvp   = (const float*)d_in[6];
    const void*  mdyn  = d_in[7];
    const void*  mma   = d_in[8];
    const float* Wq = (const float*)d_in[9];
    const float* Wk = (const float*)d_in[10];
    const float* Wv = (const float*)d_in[11];
    const float* Wo = (const float*)d_in[12];
    const float* mixW1 = (const float*)d_in[13];
    const float* mixb1 = (const float*)d_in[14];
    const float* mixW2 = (const float*)d_in[15];
    const float* mixb2 = (const float*)d_in[16];
    const float* ffW1 = (const float*)d_in[17];
    const float* ffb1 = (const float*)d_in[18];
    const float* ffW2 = (const float*)d_in[19];
    const float* ffb2 = (const float*)d_in[20];
    const float* mpW = (const float*)d_in[21];
    const float* mpB = (const float*)d_in[22];

    float* q    = symaddr_f((const void*)g_q);
    float* ctx  = symaddr_f((const void*)g_ctx);
    float* out1 = symaddr_f((const void*)g_out1);
    float* hbuf = symaddr_f((const void*)g_h);
    float* kbuf = symaddr_f((const void*)g_k);
    float* vbuf = symaddr_f((const void*)g_v);
    float* cat  = symaddr_f((const void*)g_cat);
    float* aproc = symaddr_f((const void*)g_Aproc);
    float* aoff  = symaddr_f((const void*)g_Aoff);
    float* aping = symaddr_f((const void*)g_Aprocing);
    float* aon   = symaddr_f((const void*)g_Aon);
    float* ttb   = symaddr_f((const void*)g_tt);

    static int smemSet = 0;
    if (!smemSet) {
        cudaFuncSetAttribute(gemm_grouped_kernel,
                             cudaFuncAttributeMaxDynamicSharedMemorySize,
                             SMEM_FLOATS * 4);
        smemSet = 1;
    }

    const int Rv[4] = {R0, R1, R2, R3};
    const int rowOff[4] = {0, R0, R0 + R1, R0 + R1 + R2};

    float *qB[4], *ctxB[4], *out1B[4], *hB[4], *kB[4], *vB[4];
    for (int i = 0; i < 4; i++) {
        qB[i]    = q    + (size_t)BB * rowOff[i] * EE;
        ctxB[i]  = ctx  + (size_t)BB * rowOff[i] * EE;
        out1B[i] = out1 + (size_t)BB * rowOff[i] * EE;
        hB[i]    = hbuf + (size_t)BB * rowOff[i] * FFF;
        kB[i]    = kbuf + (size_t)i * BB * NM * EE;
        vB[i]    = vbuf + (size_t)i * BB * NM * EE;
    }

    // ---- preprocessing ----
    init_kernel<<<1, 64>>>();
    detect_mask_kernel<<<64, 256>>>((const unsigned int*)mdyn, (BB * NO * NM) / 4);
    aproc_kernel<<<dim3(NO, BB), NM>>>(proc, mdyn, aproc);
    procing_tt_kernel<<<dim3(NM, BB), NM>>>(trans, mma, aping, ttb);
    minmax_kernel<<<dim3(BB, 4, 2), 256>>>(mvp, ttb);
    invnorm_apply_kernel<<<dim3(BB, 4, 2), 256>>>(mvp, ttb, aoff, aon);

    float* outF = (float*)d_out;
    float* opeOut = outF;
    float* maOut  = outF + (size_t)BB * NO * EE;
    float* vehOut = maOut + (size_t)BB * NM * EE;

    auto addGemm = [](GemmArgs& ga, const float* A, const float* W, const float* bias,
                      const float* res, float* C, int R, int K, int N, int relu,
                      int stride, int colOff) {
        GemmProb& pr = ga.p[ga.np];
        pr.A = A; pr.W = W; pr.bias = bias; pr.res = res; pr.C = C;
        pr.R = R; pr.K = K; pr.N = N; pr.relu = relu;
        pr.stride = stride; pr.colOff = colOff;
        pr.gx = N / TBN; pr.gy = R / TBM;
        int prev = ga.np ? ga.p[ga.np - 1].ctaEnd : 0;
        pr.ctaEnd = prev + pr.gx * pr.gy * BB;
        ga.np++;
    };
    auto runGemm = [](GemmArgs& ga) {
        gemm_grouped_kernel<<<ga.p[ga.np - 1].ctaEnd, 256, SMEM_FLOATS * 4>>>(ga);
    };

    // ---- phase 1: QKV for all 4 blocks ----
    {
        GemmArgs ga; ga.np = 0;
        for (int i = 0; i < 4; i++) {
            addGemm(ga, rowEmb[i], Wq + (size_t)i * EE * EE, 0, 0, qB[i], Rv[i], EE, EE, 0, EE, 0);
            addGemm(ga, maEmb,     Wk + (size_t)i * EE * EE, 0, 0, kB[i], NM,    EE, EE, 0, EE, 0);
            addGemm(ga, maEmb,     Wv + (size_t)i * EE * EE, 0, 0, vB[i], NM,    EE, EE, 0, EE, 0);
        }
        runGemm(ga);
    }

    // ---- phase 2: attention ----
    {
        const float* costs[4] = {aproc, aoff, aping, aon};
        AttnArgs aa; aa.np = 4;
        int acc = 0;
        for (int i = 0; i < 4; i++) {
            AttnProb& pr = aa.p[i];
            pr.Q = qB[i]; pr.Kp = kB[i]; pr.Vp = vB[i];
            pr.cost = costs[i]; pr.ctx = ctxB[i];
            pr.mw1 = mixW1 + (size_t)i * HH * 2 * MSS;
            pr.mb1 = mixb1 + (size_t)i * HH * MSS;
            pr.mw2 = mixW2 + (size_t)i * HH * MSS;
            pr.mb2 = mixb2 + (size_t)i * HH;
            pr.R = Rv[i];
            acc += (Rv[i] / 32) * BB * HH;
            pr.unitEnd = acc;
        }
        attn_grouped_kernel<<<acc, 256>>>(aa);
    }

    // ---- phase 3: O projection + residual + LN (fused) ----
    {
        GemmArgs ga; ga.np = 0;
        for (int i = 0; i < 4; i++)
            addGemm(ga, ctxB[i], Wo + (size_t)i * EE * EE, 0, rowEmb[i], out1B[i],
                    Rv[i], EE, EE, 0, EE, 0);
        runGemm(ga);
    }

    // ---- phase 4: FFN up (bias + relu) ----
    {
        GemmArgs ga; ga.np = 0;
        for (int i = 0; i < 4; i++)
            addGemm(ga, out1B[i], ffW1 + (size_t)i * EE * FFF, ffb1 + (size_t)i * FFF,
                    0, hB[i], Rv[i], EE, FFF, 1, FFF, 0);
        runGemm(ga);
    }

    // ---- phase 5: FFN down + bias + residual + LN (fused), write final dsts ----
    {
        float* dsts[4]    = {opeOut, vehOut, cat, cat};
        int strides[4]    = {EE, EE, 2 * EE, 2 * EE};
        int colOffs[4]    = {0, 0, 0, EE};
        GemmArgs ga; ga.np = 0;
        for (int i = 0; i < 4; i++)
            addGemm(ga, hB[i], ffW2 + (size_t)i * FFF * EE, ffb2 + (size_t)i * EE,
                    out1B[i], dsts[i], Rv[i], FFF, EE, 0, strides[i], colOffs[i]);
        runGemm(ga);
    }

    // ---- phase 6: final machine projection ----
    {
        GemmArgs ga; ga.np = 0;
        addGemm(ga, cat, mpW, mpB, 0, maOut, NM, 2 * EE, EE, 0, EE, 0);
        runGemm(ga);
    }
}